// round 17
// baseline (speedup 1.0000x reference)
#include <cuda_runtime.h>
#include <cstdint>

#define NPLANES 16384          // 64*256
#define HM 50
#define WM 50
#define HH 56
#define NTOT 51380224          // 64*256*56*56
#define PLANE_ELEMS (HM*WM)    // 2500
#define MV4 (NPLANES*PLANE_ELEMS/4)   // 10,240,000 mask float4s = 1024 * 10000
#define SCAN_BLOCKS (MV4/1024)        // 10000
#define CNT_BLOCKS (NPLANES/8)        // 2048
#define APPLY_BLOCKS (NPLANES/2)      // 8192: one block per 2 planes
#define PAIR_V4 (2*HH*14)             // 1568 float4s per 2-plane pair

typedef unsigned long long ull;

__device__ ull g_raw[NPLANES * HM];      // 6.5 MB; invariant: all-zero at entry
                                         // (static init + re-zeroed by apply)
__device__ ull g_count = 0ULL;           // invariant: 0 at entry
__device__ unsigned g_done = 0u;         // ticket, reset each launch
__device__ float g_scale;

// Pure streaming scan (proven 77% DRAM): 4 unconditional front-batched
// LDG.128 per thread, min-tree, rare global atomicOr scatter with the
// horizontal 7-dilation fused in (0x7F << col).
__global__ __launch_bounds__(256) void scan_kernel(const float4* __restrict__ mu4) {
    const float gamma = (float)(0.1 / 49.0 * 3136.0 / 2500.0);
    const int base = blockIdx.x * 1024 + threadIdx.x;

    float4 v0 = __ldcs(&mu4[base]);
    float4 v1 = __ldcs(&mu4[base + 256]);
    float4 v2 = __ldcs(&mu4[base + 512]);
    float4 v3 = __ldcs(&mu4[base + 768]);

    float m01 = fminf(fminf(fminf(v0.x, v0.y), fminf(v0.z, v0.w)),
                      fminf(fminf(v1.x, v1.y), fminf(v1.z, v1.w)));
    float m23 = fminf(fminf(fminf(v2.x, v2.y), fminf(v2.z, v2.w)),
                      fminf(fminf(v3.x, v3.y), fminf(v3.z, v3.w)));

    if (fminf(m01, m23) < gamma) {                 // rare (~2.6% of threads)
        const float4 vs[4] = {v0, v1, v2, v3};
        #pragma unroll
        for (int c = 0; c < 4; c++) {
            int eb = (base + c * 256) * 4;
            #pragma unroll
            for (int j = 0; j < 4; j++) {
                float f = (j == 0) ? vs[c].x : (j == 1) ? vs[c].y
                        : (j == 2) ? vs[c].z : vs[c].w;
                if (f < gamma) {
                    int e     = eb + j;
                    int plane = e / PLANE_ELEMS;
                    int rem   = e - plane * PLANE_ELEMS;
                    int r     = rem / WM;
                    int cc    = rem - r * WM;
                    atomicOr(&g_raw[plane * HM + r], 0x7FULL << cc);
                }
            }
        }
    }
}

// Count-only pass: warp/plane, vertical OR over [h-6,h], popcount. No
// g_blocked materialization, no writes. Last block finalizes g_scale and
// resets the counters (replay-safe).
__global__ __launch_bounds__(256) void count_kernel() {
    __shared__ int wsum[8];
    const int tid  = threadIdx.x;
    const int warp = tid >> 5;
    const int lane = tid & 31;
    const int plane = blockIdx.x * 8 + warp;

    __shared__ ull rows[8][HM];
    const ull* praw = &g_raw[(size_t)plane * HM];
    rows[warp][lane] = praw[lane];
    if (lane < HM - 32) rows[warp][lane + 32] = praw[lane + 32];
    __syncwarp();

    int cnt = 0;
    #pragma unroll
    for (int hh = 0; hh < 2; hh++) {
        int h = lane + hh * 32;
        if (h < HH) {
            int a = h - 6; if (a < 0) a = 0;
            int b = h;     if (b > HM - 1) b = HM - 1;
            ull o = 0ULL;
            for (int r = a; r <= b; r++) o |= rows[warp][r];
            cnt += __popcll(o);
        }
    }
    #pragma unroll
    for (int off = 16; off; off >>= 1)
        cnt += __shfl_down_sync(0xFFFFFFFFu, cnt, off);
    if (lane == 0) wsum[warp] = cnt;
    __syncthreads();

    if (tid == 0) {
        int s = 0;
        #pragma unroll
        for (int w = 0; w < 8; w++) s += wsum[w];
        atomicAdd(&g_count, (ull)s);
        __threadfence();
        unsigned ticket = atomicAdd(&g_done, 1u);
        if (ticket == CNT_BLOCKS - 1) {
            ull c = atomicAdd(&g_count, 0ULL);
            g_scale = (float)((double)NTOT / (double)(NTOT - (long long)c));
            g_count = 0ULL;
            g_done  = 0u;
        }
    }
}

// Apply, one block per 2 planes. Prologue: stage 100 g_raw words (L2-hot),
// re-zero them (restores replay invariant), build 112 dilated row words in
// smem. Main: 6-7 float4s/thread, one LDS per float4 for mask bits.
__global__ __launch_bounds__(256) void apply_kernel(const float4* __restrict__ x4,
                                                    float4* __restrict__ out4) {
    __shared__ ull raw[2 * HM];     // 100 words
    __shared__ ull dil[2 * HH];     // 112 dilated words

    const int tid = threadIdx.x;
    const float s = g_scale;

    ull* praw = &g_raw[(size_t)blockIdx.x * (2 * HM)];
    if (tid < 2 * HM) {
        raw[tid] = praw[tid];
        praw[tid] = 0ULL;           // re-zero for next graph replay
    }
    __syncthreads();

    if (tid < 2 * HH) {
        int pl = tid / HH;
        int h  = tid - pl * HH;
        int a = h - 6; if (a < 0) a = 0;
        int b = h;     if (b > HM - 1) b = HM - 1;
        ull o = 0ULL;
        for (int r = a; r <= b; r++) o |= raw[pl * HM + r];
        dil[tid] = o;
    }
    __syncthreads();

    const float4* px = x4   + (size_t)blockIdx.x * PAIR_V4;
    float4*       po = out4 + (size_t)blockIdx.x * PAIR_V4;

    #pragma unroll
    for (int k = 0; k < 7; k++) {
        int i = tid + k * 256;
        if (k == 6 && i >= PAIR_V4) break;        // tail: only tid<32 do k==6
        int rowl = i / 14;                        // 0..111 local row
        int c4   = i - rowl * 14;
        unsigned bits = (unsigned)(dil[rowl] >> (c4 * 4)) & 0xFu;

        float4 xi = __ldcs(&px[i]);
        float4 o;
        o.x = (bits & 1u) ? 0.0f : xi.x * s;
        o.y = (bits & 2u) ? 0.0f : xi.y * s;
        o.z = (bits & 4u) ? 0.0f : xi.z * s;
        o.w = (bits & 8u) ? 0.0f : xi.w * s;
        __stcs(&po[i], o);
    }
}

extern "C" void kernel_launch(void* const* d_in, const int* in_sizes, int n_in,
                              void* d_out, int out_size) {
    const float* x      = (const float*)d_in[0];
    const float* mask_u = (const float*)d_in[1];
    float* out          = (float*)d_out;

    scan_kernel<<<SCAN_BLOCKS, 256>>>((const float4*)mask_u);
    count_kernel<<<CNT_BLOCKS, 256>>>();
    apply_kernel<<<APPLY_BLOCKS, 256>>>((const float4*)x, (float4*)out);
}